// round 3
// baseline (speedup 1.0000x reference)
#include <cuda_runtime.h>
#include <stdint.h>

#define NPTS 8192
#define DIM  64
#define KSEL 40
#define SLOPE 0.01f

// ---------------- scratch (static __device__ per allocation rules) ----------
__device__ float g_f[NPTS * DIM];
__device__ float g_sq[NPTS];
__device__ float g_t[2][NPTS * DIM];
__device__ float g_c[2][NPTS * DIM];
__device__ float g_dist[(size_t)NPTS * NPTS];   // 256 MB
__device__ int   g_idx[NPTS * KSEL];
__device__ float g_h[NPTS * 192];               // [h1 | h2 | hmax]

__device__ __forceinline__ float leaky(float x) { return x >= 0.f ? x : SLOPE * x; }

// ---------------- kernel 1: f = feature @ Wb.T + bb ; sq = sum(f*f) --------
__global__ void __launch_bounds__(256) k_f(const float* __restrict__ feat,
                                           const float* __restrict__ Wb,
                                           const float* __restrict__ bb) {
    __shared__ float fs[32][256];   // 32 input rows
    __shared__ float fo[32][64];    // f outputs for sq reduction
    int tid = threadIdx.x;
    int r0 = blockIdx.x * 32;
    for (int i = tid; i < 32 * 256; i += 256) {
        int r = i >> 8, k = i & 255;
        fs[r][k] = feat[(size_t)(r0 + r) * 256 + k];
    }
    __syncthreads();
    int o  = tid & 63;
    int rg = tid >> 6;        // 4 groups of 8 rows
    float acc[8];
#pragma unroll
    for (int i = 0; i < 8; i++) acc[i] = bb[o];
    for (int c = 0; c < 4; c++) {
        float4 w4[16];
        const float4* wp = (const float4*)(Wb + o * 256 + c * 64);
#pragma unroll
        for (int i = 0; i < 16; i++) w4[i] = wp[i];
#pragma unroll
        for (int rr = 0; rr < 8; rr++) {
            int r = rg * 8 + rr;
            const float4* xs = (const float4*)(&fs[r][c * 64]);
            float a = 0.f;
#pragma unroll
            for (int i = 0; i < 16; i++) {
                float4 x = xs[i];
                a += x.x * w4[i].x + x.y * w4[i].y + x.z * w4[i].z + x.w * w4[i].w;
            }
            acc[rr] += a;
        }
    }
#pragma unroll
    for (int rr = 0; rr < 8; rr++) {
        int r = rg * 8 + rr;
        g_f[(size_t)(r0 + r) * 64 + o] = acc[rr];
        fo[r][o] = acc[rr];
    }
    __syncthreads();
    if (tid < 32) {                 // deterministic per-row square sum
        float s = 0.f;
#pragma unroll
        for (int k = 0; k < 64; k++) { float v = fo[tid][k]; s += v * v; }
        g_sq[r0 + tid] = s;
    }
}

// ---------------- kernel 2: t = f@Wt.T ; c = f@(Wp+Wt).T + bp + bt ---------
__global__ void __launch_bounds__(256) k_aux(const float* __restrict__ Wt1, const float* __restrict__ bt1,
                                             const float* __restrict__ Wp1, const float* __restrict__ bp1,
                                             const float* __restrict__ Wt2, const float* __restrict__ bt2,
                                             const float* __restrict__ Wp2, const float* __restrict__ bp2) {
    int set = blockIdx.y;
    const float* Wt = set ? Wt2 : Wt1;
    const float* bt = set ? bt2 : bt1;
    const float* Wp = set ? Wp2 : Wp1;
    const float* bp = set ? bp2 : bp1;

    __shared__ float fs[16][64];
    int tid = threadIdx.x;
    int r0 = blockIdx.x * 16;
    for (int i = tid; i < 16 * 64; i += 256) fs[i >> 6][i & 63] = g_f[(size_t)r0 * 64 + i];
    __syncthreads();
    int o = tid & 63, rg = tid >> 6;   // 4 rows per group
    float bsum = bt[o] + bp[o];

    float4 w4[16];
    const float4* wtp = (const float4*)(Wt + o * 64);
#pragma unroll
    for (int i = 0; i < 16; i++) w4[i] = wtp[i];
    float at[4];
#pragma unroll
    for (int rr = 0; rr < 4; rr++) {
        int r = rg * 4 + rr;
        const float4* xs = (const float4*)(&fs[r][0]);
        float a = 0.f;
#pragma unroll
        for (int i = 0; i < 16; i++) {
            float4 x = xs[i];
            a += x.x * w4[i].x + x.y * w4[i].y + x.z * w4[i].z + x.w * w4[i].w;
        }
        at[rr] = a;
        g_t[set][(size_t)(r0 + r) * 64 + o] = a;
    }
    const float4* wpp = (const float4*)(Wp + o * 64);
#pragma unroll
    for (int i = 0; i < 16; i++) w4[i] = wpp[i];
#pragma unroll
    for (int rr = 0; rr < 4; rr++) {
        int r = rg * 4 + rr;
        const float4* xs = (const float4*)(&fs[r][0]);
        float a = 0.f;
#pragma unroll
        for (int i = 0; i < 16; i++) {
            float4 x = xs[i];
            a += x.x * w4[i].x + x.y * w4[i].y + x.z * w4[i].z + x.w * w4[i].w;
        }
        g_c[set][(size_t)(r0 + r) * 64 + o] = at[rr] + a + bsum;
    }
}

// ---------------- kernel 3: pairwise distances, 128x128 tiles, 8x8/thread --
__global__ void __launch_bounds__(256) k_dist() {
    __shared__ float As[32][133];   // [k][row], pad 133 (coprime 32)
    __shared__ float Bs[32][133];
    __shared__ float sqa[128], sqb[128];
    int tid = threadIdx.x;
    int tx = tid & 15, ty = tid >> 4;
    int i0 = blockIdx.y * 128, j0 = blockIdx.x * 128;
    if (tid < 128) sqa[tid] = g_sq[i0 + tid];
    else           sqb[tid - 128] = g_sq[j0 + tid - 128];

    float acc[8][8] = {};
    for (int kk = 0; kk < 2; kk++) {
        __syncthreads();
        for (int idx = tid; idx < 4096; idx += 256) {
            int r = idx >> 5, k = idx & 31;
            As[k][r] = g_f[(size_t)(i0 + r) * 64 + kk * 32 + k];
            Bs[k][r] = g_f[(size_t)(j0 + r) * 64 + kk * 32 + k];
        }
        __syncthreads();
#pragma unroll
        for (int k = 0; k < 32; k++) {
            float a[8], b[8];
#pragma unroll
            for (int i = 0; i < 8; i++) a[i] = As[k][ty + 16 * i];
#pragma unroll
            for (int j = 0; j < 8; j++) b[j] = Bs[k][tx + 16 * j];
#pragma unroll
            for (int i = 0; i < 8; i++)
#pragma unroll
                for (int j = 0; j < 8; j++) acc[i][j] += a[i] * b[j];
        }
    }
#pragma unroll
    for (int i = 0; i < 8; i++) {
        int row = i0 + ty + 16 * i;
        float si = sqa[ty + 16 * i];
        float* orow = &g_dist[(size_t)row * NPTS + j0];
#pragma unroll
        for (int j = 0; j < 8; j++)
            orow[tx + 16 * j] = si + sqb[tx + 16 * j] - 2.f * acc[i][j];
    }
}

// ---------------- kernel 4: exact sorted top-40 (sample-threshold select) --
__device__ __forceinline__ unsigned fkey(float v) {
    unsigned b = __float_as_uint(v);
    return (b & 0x80000000u) ? ~b : (b | 0x80000000u);
}

__global__ void __launch_bounds__(256) k_select() {
    __shared__ unsigned samp[256];               // 1 KB
    __shared__ unsigned long long cand[1024];    // 8 KB
    __shared__ int scnt;

    int tid = threadIdx.x;
    int lane = tid & 31;
    int row = blockIdx.x;
    const float* drow = &g_dist[(size_t)row * NPTS];
    const float4* d4p = (const float4*)drow;

    // sample 256 keys straight from global, bitonic-sort ascending
    samp[tid] = fkey(drow[tid * 32 + 16]);
    __syncthreads();
    for (int size = 2; size <= 256; size <<= 1) {
        for (int stride = size >> 1; stride > 0; stride >>= 1) {
            int i = tid, ixj = i ^ stride;
            if (ixj > i) {
                bool up = (i & size) == 0;
                unsigned a = samp[i], b = samp[ixj];
                if ((a > b) == up) { samp[i] = b; samp[ixj] = a; }
            }
            __syncthreads();
        }
    }

    // threshold = r-th smallest sample; stream row, warp-aggregated compaction
    int C = 0;
    int r = 8;                        // expected ~290 keys below samp[8]
    for (int attempt = 0; attempt < 12; attempt++) {
        __syncthreads();
        if (tid == 0) scnt = 0;
        __syncthreads();
        unsigned T = samp[r];
        for (int q = tid; q < NPTS / 4; q += 256) {
            float4 d4 = d4p[q];
            unsigned kk[4] = { fkey(d4.x), fkey(d4.y), fkey(d4.z), fkey(d4.w) };
#pragma unroll
            for (int e = 0; e < 4; e++) {
                bool p = kk[e] < T;
                unsigned m = __ballot_sync(0xFFFFFFFFu, p);
                if (m) {
                    int leader = __ffs(m) - 1;
                    int base = 0;
                    if (lane == leader) base = atomicAdd(&scnt, __popc(m));
                    base = __shfl_sync(0xFFFFFFFFu, base, leader);
                    if (p) {
                        int pos = base + __popc(m & ((1u << lane) - 1u));
                        if (pos < 1024)
                            cand[pos] = ((unsigned long long)kk[e] << 32) | (unsigned)(q * 4 + e);
                    }
                }
            }
        }
        __syncthreads();
        C = scnt;
        if (C >= KSEL && C <= 1024) break;
        if (C < KSEL) r = (r * 2 > 255) ? 255 : r * 2;
        else          r = (r <= 1) ? 1 : (r >> 1);
    }
    int Cc = C < 1024 ? C : 1024;
    int S = 64;
    while (S < Cc) S <<= 1;          // S in {64..1024}
    for (int i = Cc + tid; i < S; i += 256) cand[i] = 0xFFFFFFFFFFFFFFFFull;
    __syncthreads();

    // bitonic sort S candidates: (key asc, idx asc) via packed compare
    for (int size = 2; size <= S; size <<= 1) {
        for (int stride = size >> 1; stride > 0; stride >>= 1) {
            for (int i = tid; i < S; i += 256) {
                int ixj = i ^ stride;
                if (ixj > i) {
                    bool up = (i & size) == 0;
                    unsigned long long a = cand[i], b = cand[ixj];
                    if ((a > b) == up) { cand[i] = b; cand[ixj] = a; }
                }
            }
            __syncthreads();
        }
    }
    if (tid < KSEL) g_idx[row * KSEL + tid] = (int)(cand[tid] & 0xFFFFFFFFull);
}

// ---------------- kernel 5: hmax over first 9 neighbors --------------------
__global__ void __launch_bounds__(64) k_hmax() {
    __shared__ int nb[9];
    int node = blockIdx.x;
    int o = threadIdx.x;
    if (o < 9) nb[o] = g_idx[node * KSEL + o];
    __syncthreads();
    float m = -3.4e38f;
#pragma unroll
    for (int j = 0; j < 9; j++) m = fmaxf(m, g_f[(size_t)nb[j] * 64 + o]);
    g_h[(size_t)node * 192 + 128 + o] = m;
}

// ---------------- kernel 6: edge conv, 8 nodes per block -------------------
#define ENODES 8
__global__ void __launch_bounds__(128) k_edge(const float* __restrict__ Wa1, const float* __restrict__ ba1,
                                              const float* __restrict__ Wb1, const float* __restrict__ bb1,
                                              const float* __restrict__ Wa2, const float* __restrict__ ba2,
                                              const float* __restrict__ Wb2, const float* __restrict__ bb2) {
    int cv = blockIdx.y;
    const float* Wa  = cv ? Wa2 : Wa1;
    const float* ba  = cv ? ba2 : ba1;
    const float* Wb_ = cv ? Wb2 : Wb1;
    const float* bbv = cv ? bb2 : bb1;

    __shared__ float W1s[64][65];   // [k][o] transposed
    __shared__ float W2s[64][65];
    __shared__ float zs[20][64];
    __shared__ float y1s[20][64];
    __shared__ float cs[64];
    __shared__ int   nb[20];
    __shared__ float pm[2][64];

    int tid = threadIdx.x;
    for (int i = tid; i < 4096; i += 128) {
        int o = i >> 6, k = i & 63;
        W1s[k][o] = Wa[i];
        W2s[k][o] = Wb_[i];
    }
    int o = tid & 63, half = tid >> 6;
    float b1o = ba[o], b2o = bbv[o];

    for (int nn = 0; nn < ENODES; nn++) {
        int node = blockIdx.x * ENODES + nn;
        __syncthreads();   // also covers initial weight-staging barrier
        if (tid < 64) cs[tid] = g_c[cv][(size_t)node * 64 + tid];
        if (tid < 20) nb[tid] = g_idx[node * KSEL + (cv ? tid * 2 : tid)];
        __syncthreads();

        for (int e = tid; e < 20 * 64; e += 128) {
            int j = e >> 6, k = e & 63;
            zs[j][k] = leaky(cs[k] - g_t[cv][(size_t)nb[j] * 64 + k]);
        }
        __syncthreads();

        float w[64];
#pragma unroll
        for (int k = 0; k < 64; k++) w[k] = W1s[k][o];
        for (int j = half * 10; j < half * 10 + 10; j++) {
            float a = 0.f;
#pragma unroll
            for (int k = 0; k < 64; k += 4) {
                float4 z4 = *(const float4*)&zs[j][k];
                a += z4.x * w[k] + z4.y * w[k + 1] + z4.z * w[k + 2] + z4.w * w[k + 3];
            }
            y1s[j][o] = leaky(a + b1o);
        }
        __syncthreads();
#pragma unroll
        for (int k = 0; k < 64; k++) w[k] = W2s[k][o];
        float m = -3.4e38f;
        for (int j = half * 10; j < half * 10 + 10; j++) {
            float a = 0.f;
#pragma unroll
            for (int k = 0; k < 64; k += 4) {
                float4 y4 = *(const float4*)&y1s[j][k];
                a += y4.x * w[k] + y4.y * w[k + 1] + y4.z * w[k + 2] + y4.w * w[k + 3];
            }
            m = fmaxf(m, a + b2o);
        }
        pm[half][o] = m;
        __syncthreads();
        if (tid < 64)
            g_h[(size_t)node * 192 + cv * 64 + tid] = fmaxf(pm[0][tid], pm[1][tid]);
    }
}

// ---------------- kernel 7: out = [h1|h2|hmax] @ Wl.T + bl + feature -------
__global__ void __launch_bounds__(256) k_final(const float* __restrict__ Wl,
                                               const float* __restrict__ bl,
                                               const float* __restrict__ feat,
                                               float* __restrict__ out) {
    __shared__ float hs[16][192];
    int tid = threadIdx.x;
    int r0 = blockIdx.x * 16;
    for (int i = tid; i < 16 * 192; i += 256) hs[i / 192][i % 192] = g_h[(size_t)r0 * 192 + i];
    __syncthreads();
    int o = tid;           // 256 outputs
    float acc[16] = {};
    for (int c = 0; c < 3; c++) {
        float4 w4[16];
        const float4* wp = (const float4*)(Wl + o * 192 + c * 64);
#pragma unroll
        for (int i = 0; i < 16; i++) w4[i] = wp[i];
#pragma unroll
        for (int r = 0; r < 16; r++) {
            const float4* xs = (const float4*)(&hs[r][c * 64]);
            float a = 0.f;
#pragma unroll
            for (int i = 0; i < 16; i++) {
                float4 x = xs[i];
                a += x.x * w4[i].x + x.y * w4[i].y + x.z * w4[i].z + x.w * w4[i].w;
            }
            acc[r] += a;
        }
    }
    float b = bl[o];
#pragma unroll
    for (int r = 0; r < 16; r++)
        out[(size_t)(r0 + r) * 256 + o] = acc[r] + b + feat[(size_t)(r0 + r) * 256 + o];
}

// ---------------- launch ---------------------------------------------------
extern "C" void kernel_launch(void* const* d_in, const int* in_sizes, int n_in,
                              void* d_out, int out_size) {
    const float* feature = (const float*)d_in[0];
    const float* Wb   = (const float*)d_in[1];
    const float* bb   = (const float*)d_in[2];
    const float* Wt1  = (const float*)d_in[3];
    const float* bt1  = (const float*)d_in[4];
    const float* Wp1  = (const float*)d_in[5];
    const float* bp1  = (const float*)d_in[6];
    const float* Wm1a = (const float*)d_in[7];
    const float* bm1a = (const float*)d_in[8];
    const float* Wm1b = (const float*)d_in[9];
    const float* bm1b = (const float*)d_in[10];
    const float* Wt2  = (const float*)d_in[11];
    const float* bt2  = (const float*)d_in[12];
    const float* Wp2  = (const float*)d_in[13];
    const float* bp2  = (const float*)d_in[14];
    const float* Wm2a = (const float*)d_in[15];
    const float* bm2a = (const float*)d_in[16];
    const float* Wm2b = (const float*)d_in[17];
    const float* bm2b = (const float*)d_in[18];
    const float* Wl   = (const float*)d_in[19];
    const float* bl   = (const float*)d_in[20];
    float* out = (float*)d_out;

    k_f<<<NPTS / 32, 256>>>(feature, Wb, bb);
    k_aux<<<dim3(NPTS / 16, 2), 256>>>(Wt1, bt1, Wp1, bp1, Wt2, bt2, Wp2, bp2);
    k_dist<<<dim3(NPTS / 128, NPTS / 128), 256>>>();
    k_select<<<NPTS, 256>>>();
    k_hmax<<<NPTS, 64>>>();
    k_edge<<<dim3(NPTS / ENODES, 2), 128>>>(Wm1a, bm1a, Wm1b, bm1b, Wm2a, bm2a, Wm2b, bm2b);
    k_final<<<NPTS / 16, 256>>>(Wl, bl, feature, out);
}

// round 4
// speedup vs baseline: 1.1716x; 1.1716x over previous
#include <cuda_runtime.h>
#include <stdint.h>

#define NPTS 8192
#define DIM  64
#define KSEL 40
#define SLOPE 0.01f

// ---------------- scratch (static __device__ per allocation rules) ----------
__device__ float g_f[NPTS * DIM];
__device__ float g_sq[NPTS];
__device__ float g_t[2][NPTS * DIM];
__device__ float g_c[2][NPTS * DIM];
__device__ float g_dist[(size_t)NPTS * NPTS];   // 256 MB
__device__ int   g_idx[NPTS * KSEL];
__device__ float g_h[NPTS * 192];               // [h1 | h2 | hmax]

__device__ __forceinline__ float leaky(float x) { return x >= 0.f ? x : SLOPE * x; }

// ---------------- kernel 1: f = feature @ Wb.T + bb ; sq = sum(f*f) --------
__global__ void __launch_bounds__(256) k_f(const float* __restrict__ feat,
                                           const float* __restrict__ Wb,
                                           const float* __restrict__ bb) {
    __shared__ float fs[32][256];   // 32 input rows
    __shared__ float fo[32][64];    // f outputs for sq reduction
    int tid = threadIdx.x;
    int r0 = blockIdx.x * 32;
    for (int i = tid; i < 32 * 256; i += 256) {
        int r = i >> 8, k = i & 255;
        fs[r][k] = feat[(size_t)(r0 + r) * 256 + k];
    }
    __syncthreads();
    int o  = tid & 63;
    int rg = tid >> 6;        // 4 groups of 8 rows
    float acc[8];
#pragma unroll
    for (int i = 0; i < 8; i++) acc[i] = bb[o];
    for (int c = 0; c < 4; c++) {
        float4 w4[16];
        const float4* wp = (const float4*)(Wb + o * 256 + c * 64);
#pragma unroll
        for (int i = 0; i < 16; i++) w4[i] = wp[i];
#pragma unroll
        for (int rr = 0; rr < 8; rr++) {
            int r = rg * 8 + rr;
            const float4* xs = (const float4*)(&fs[r][c * 64]);
            float a = 0.f;
#pragma unroll
            for (int i = 0; i < 16; i++) {
                float4 x = xs[i];
                a += x.x * w4[i].x + x.y * w4[i].y + x.z * w4[i].z + x.w * w4[i].w;
            }
            acc[rr] += a;
        }
    }
#pragma unroll
    for (int rr = 0; rr < 8; rr++) {
        int r = rg * 8 + rr;
        g_f[(size_t)(r0 + r) * 64 + o] = acc[rr];
        fo[r][o] = acc[rr];
    }
    __syncthreads();
    if (tid < 32) {                 // deterministic per-row square sum
        float s = 0.f;
#pragma unroll
        for (int k = 0; k < 64; k++) { float v = fo[tid][k]; s += v * v; }
        g_sq[r0 + tid] = s;
    }
}

// ---------------- kernel 2: t = f@Wt.T ; c = f@(Wp+Wt).T + bp + bt ---------
__global__ void __launch_bounds__(256) k_aux(const float* __restrict__ Wt1, const float* __restrict__ bt1,
                                             const float* __restrict__ Wp1, const float* __restrict__ bp1,
                                             const float* __restrict__ Wt2, const float* __restrict__ bt2,
                                             const float* __restrict__ Wp2, const float* __restrict__ bp2) {
    int set = blockIdx.y;
    const float* Wt = set ? Wt2 : Wt1;
    const float* bt = set ? bt2 : bt1;
    const float* Wp = set ? Wp2 : Wp1;
    const float* bp = set ? bp2 : bp1;

    __shared__ float fs[16][64];
    int tid = threadIdx.x;
    int r0 = blockIdx.x * 16;
    for (int i = tid; i < 16 * 64; i += 256) fs[i >> 6][i & 63] = g_f[(size_t)r0 * 64 + i];
    __syncthreads();
    int o = tid & 63, rg = tid >> 6;   // 4 rows per group
    float bsum = bt[o] + bp[o];

    float4 w4[16];
    const float4* wtp = (const float4*)(Wt + o * 64);
#pragma unroll
    for (int i = 0; i < 16; i++) w4[i] = wtp[i];
    float at[4];
#pragma unroll
    for (int rr = 0; rr < 4; rr++) {
        int r = rg * 4 + rr;
        const float4* xs = (const float4*)(&fs[r][0]);
        float a = 0.f;
#pragma unroll
        for (int i = 0; i < 16; i++) {
            float4 x = xs[i];
            a += x.x * w4[i].x + x.y * w4[i].y + x.z * w4[i].z + x.w * w4[i].w;
        }
        at[rr] = a;
        g_t[set][(size_t)(r0 + r) * 64 + o] = a;
    }
    const float4* wpp = (const float4*)(Wp + o * 64);
#pragma unroll
    for (int i = 0; i < 16; i++) w4[i] = wpp[i];
#pragma unroll
    for (int rr = 0; rr < 4; rr++) {
        int r = rg * 4 + rr;
        const float4* xs = (const float4*)(&fs[r][0]);
        float a = 0.f;
#pragma unroll
        for (int i = 0; i < 16; i++) {
            float4 x = xs[i];
            a += x.x * w4[i].x + x.y * w4[i].y + x.z * w4[i].z + x.w * w4[i].w;
        }
        g_c[set][(size_t)(r0 + r) * 64 + o] = at[rr] + a + bsum;
    }
}

// ---------------- kernel 3: pairwise distances, symmetric (upper + mirror) -
__global__ void __launch_bounds__(256) k_dist() {
    int bj = blockIdx.x, bi = blockIdx.y;
    if (bi > bj) return;                 // symmetry: compute upper triangle only

    __shared__ float As[64][65];
    __shared__ float Bs[64][65];
    __shared__ float sqa[64], sqb[64];
    int tid = threadIdx.x;
    int tx = tid & 15, ty = tid >> 4;
    int i0 = bi * 64, j0 = bj * 64;
    for (int i = tid; i < 64 * 64; i += 256) {
        int r = i >> 6, k = i & 63;
        As[r][k] = g_f[(size_t)(i0 + r) * 64 + k];
        Bs[r][k] = g_f[(size_t)(j0 + r) * 64 + k];
    }
    if (tid < 64) sqa[tid] = g_sq[i0 + tid];
    else if (tid < 128) sqb[tid - 64] = g_sq[j0 + tid - 64];
    __syncthreads();

    float acc[4][4] = {};
#pragma unroll 16
    for (int k = 0; k < 64; k++) {
        float a[4], b[4];
#pragma unroll
        for (int i = 0; i < 4; i++) a[i] = As[ty * 4 + i][k];
#pragma unroll
        for (int i = 0; i < 4; i++) b[i] = Bs[tx * 4 + i][k];
#pragma unroll
        for (int i = 0; i < 4; i++)
#pragma unroll
            for (int j = 0; j < 4; j++) acc[i][j] += a[i] * b[j];
    }
    float dv[4][4];
#pragma unroll
    for (int i = 0; i < 4; i++) {
        float si = sqa[ty * 4 + i];
#pragma unroll
        for (int j = 0; j < 4; j++) dv[i][j] = si + sqb[tx * 4 + j] - 2.f * acc[i][j];
    }
#pragma unroll
    for (int i = 0; i < 4; i++) {
        float4 d = make_float4(dv[i][0], dv[i][1], dv[i][2], dv[i][3]);
        *(float4*)&g_dist[(size_t)(i0 + ty * 4 + i) * NPTS + j0 + tx * 4] = d;
    }
    if (bi != bj) {
#pragma unroll
        for (int j = 0; j < 4; j++) {
            float4 m = make_float4(dv[0][j], dv[1][j], dv[2][j], dv[3][j]);
            *(float4*)&g_dist[(size_t)(j0 + tx * 4 + j) * NPTS + i0 + ty * 4] = m;
        }
    }
}

// ---------------- kernel 4: exact sorted top-40 (lean sample select) -------
__device__ __forceinline__ unsigned fkey(float v) {
    unsigned b = __float_as_uint(v);
    return (b & 0x80000000u) ? ~b : (b | 0x80000000u);
}

__global__ void __launch_bounds__(256) k_select() {
    __shared__ float ssamp[256];                 // per-warp sorted samples
    __shared__ unsigned long long cand[1024];    // 8 KB
    __shared__ int scnt;
    __shared__ float sT;

    int tid  = threadIdx.x;
    int lane = tid & 31;
    int w    = tid >> 5;
    int row  = blockIdx.x;
    const float* drow = &g_dist[(size_t)row * NPTS];
    const float4* d4p = (const float4*)drow;

    // --- 256 samples; per-warp in-register bitonic sort (ascending by lane)
    float v = drow[tid * 32 + 16];
#pragma unroll
    for (int k = 2; k <= 32; k <<= 1) {
#pragma unroll
        for (int j = k >> 1; j > 0; j >>= 1) {
            float o = __shfl_xor_sync(0xFFFFFFFFu, v, j);
            bool takeMin = (((lane & k) == 0) == ((lane & j) == 0));
            v = takeMin ? fminf(v, o) : fmaxf(v, o);
        }
    }
    ssamp[w * 32 + lane] = v;
    __syncthreads();

    // --- warp 0: T = 5th smallest of union(per-warp top-5) = global samp[4]
    if (w == 0) {
        int i1 = 32 + lane;
        float a = ssamp[(lane / 5) * 32 + (lane % 5)];
        float b = (lane < 8) ? ssamp[(i1 / 5) * 32 + (i1 % 5)] : 3.4e38f;
        float T = 0.f;
#pragma unroll
        for (int it = 0; it < 5; it++) {
            float m = fminf(a, b);
#pragma unroll
            for (int s = 16; s; s >>= 1) m = fminf(m, __shfl_xor_sync(0xFFFFFFFFu, m, s));
            unsigned own = __ballot_sync(0xFFFFFFFFu, a == m || b == m);
            int first = __ffs(own) - 1;
            if (lane == first) { if (a == m) a = 3.4e38f; else b = 3.4e38f; }
            T = m;
        }
        if (lane == 0) sT = T;
    }
    __syncthreads();

    // --- stream row, warp-scan compaction; rare fallback ladder on failure
    float T = sT;
    int C = 0;
    bool fallback_sorted = false;
    int r = 4;
    for (int attempt = 0; attempt < 16; attempt++) {
        __syncthreads();
        if (tid == 0) scnt = 0;
        __syncthreads();
        for (int q = tid; q < NPTS / 4; q += 256) {
            float4 d = d4p[q];
            bool p0 = d.x < T, p1 = d.y < T, p2 = d.z < T, p3 = d.w < T;
            int cnt = (int)p0 + (int)p1 + (int)p2 + (int)p3;
            unsigned bm = __ballot_sync(0xFFFFFFFFu, cnt != 0);
            if (!bm) continue;
            int off = cnt;
#pragma unroll
            for (int s = 1; s < 32; s <<= 1) {
                int t2 = __shfl_up_sync(0xFFFFFFFFu, off, s);
                if (lane >= s) off += t2;
            }
            int tot = __shfl_sync(0xFFFFFFFFu, off, 31);
            int base = 0;
            if (lane == 31) base = atomicAdd(&scnt, tot);
            base = __shfl_sync(0xFFFFFFFFu, base, 31);
            int pos = base + off - cnt;
            int j = q * 4;
            if (p0) { if (pos < 1024) cand[pos] = ((unsigned long long)fkey(d.x) << 32) | (unsigned)(j + 0); pos++; }
            if (p1) { if (pos < 1024) cand[pos] = ((unsigned long long)fkey(d.y) << 32) | (unsigned)(j + 1); pos++; }
            if (p2) { if (pos < 1024) cand[pos] = ((unsigned long long)fkey(d.z) << 32) | (unsigned)(j + 2); pos++; }
            if (p3) { if (pos < 1024) cand[pos] = ((unsigned long long)fkey(d.w) << 32) | (unsigned)(j + 3); pos++; }
        }
        __syncthreads();
        C = scnt;
        if (C >= KSEL && C <= 1024) break;
        // rare path: sort all 256 samples once, then walk rank ladder
        if (!fallback_sorted) {
            fallback_sorted = true;
            for (int size = 2; size <= 256; size <<= 1) {
                for (int stride = size >> 1; stride > 0; stride >>= 1) {
                    __syncthreads();
                    int i = tid, ixj = i ^ stride;
                    if (ixj > i) {
                        float x = ssamp[i], y = ssamp[ixj];
                        bool up = (i & size) == 0;
                        if ((x > y) == up) { ssamp[i] = y; ssamp[ixj] = x; }
                    }
                }
            }
            __syncthreads();
        }
        if (C < KSEL) r = (r * 3 > 255) ? 255 : r * 3;
        else          r = (r <= 1) ? 1 : (r >> 1);
        T = ssamp[r];
        __syncthreads();
    }

    int Cc = C < 1024 ? C : 1024;
    int S = 64;
    while (S < Cc) S <<= 1;          // S in {64..1024}
    for (int i = Cc + tid; i < S; i += 256) cand[i] = 0xFFFFFFFFFFFFFFFFull;
    __syncthreads();

    // bitonic sort S candidates: (key asc, idx asc) via packed compare
    for (int size = 2; size <= S; size <<= 1) {
        for (int stride = size >> 1; stride > 0; stride >>= 1) {
            for (int i = tid; i < S; i += 256) {
                int ixj = i ^ stride;
                if (ixj > i) {
                    bool up = (i & size) == 0;
                    unsigned long long a = cand[i], b = cand[ixj];
                    if ((a > b) == up) { cand[i] = b; cand[ixj] = a; }
                }
            }
            __syncthreads();
        }
    }
    if (tid < KSEL) g_idx[row * KSEL + tid] = (int)(cand[tid] & 0xFFFFFFFFull);
}

// ---------------- kernel 5: hmax over first 9 neighbors --------------------
__global__ void __launch_bounds__(64) k_hmax() {
    __shared__ int nb[9];
    int node = blockIdx.x;
    int o = threadIdx.x;
    if (o < 9) nb[o] = g_idx[node * KSEL + o];
    __syncthreads();
    float m = -3.4e38f;
#pragma unroll
    for (int j = 0; j < 9; j++) m = fmaxf(m, g_f[(size_t)nb[j] * 64 + o]);
    g_h[(size_t)node * 192 + 128 + o] = m;
}

// ---------------- kernel 6: edge conv, 8 nodes per block -------------------
#define ENODES 8
__global__ void __launch_bounds__(128) k_edge(const float* __restrict__ Wa1, const float* __restrict__ ba1,
                                              const float* __restrict__ Wb1, const float* __restrict__ bb1,
                                              const float* __restrict__ Wa2, const float* __restrict__ ba2,
                                              const float* __restrict__ Wb2, const float* __restrict__ bb2) {
    int cv = blockIdx.y;
    const float* Wa  = cv ? Wa2 : Wa1;
    const float* ba  = cv ? ba2 : ba1;
    const float* Wb_ = cv ? Wb2 : Wb1;
    const float* bbv = cv ? bb2 : bb1;

    __shared__ float W1s[64][65];   // [k][o] transposed
    __shared__ float W2s[64][65];
    __shared__ float zs[20][64];
    __shared__ float y1s[20][64];
    __shared__ float cs[64];
    __shared__ int   nb[20];
    __shared__ float pm[2][64];

    int tid = threadIdx.x;
    for (int i = tid; i < 4096; i += 128) {
        int o = i >> 6, k = i & 63;
        W1s[k][o] = Wa[i];
        W2s[k][o] = Wb_[i];
    }
    int o = tid & 63, half = tid >> 6;
    float b1o = ba[o], b2o = bbv[o];

    for (int nn = 0; nn < ENODES; nn++) {
        int node = blockIdx.x * ENODES + nn;
        __syncthreads();   // also covers initial weight-staging barrier
        if (tid < 64) cs[tid] = g_c[cv][(size_t)node * 64 + tid];
        if (tid < 20) nb[tid] = g_idx[node * KSEL + (cv ? tid * 2 : tid)];
        __syncthreads();

        for (int e = tid; e < 20 * 64; e += 128) {
            int j = e >> 6, k = e & 63;
            zs[j][k] = leaky(cs[k] - g_t[cv][(size_t)nb[j] * 64 + k]);
        }
        __syncthreads();

        float w[64];
#pragma unroll
        for (int k = 0; k < 64; k++) w[k] = W1s[k][o];
        for (int j = half * 10; j < half * 10 + 10; j++) {
            float a = 0.f;
#pragma unroll
            for (int k = 0; k < 64; k += 4) {
                float4 z4 = *(const float4*)&zs[j][k];
                a += z4.x * w[k] + z4.y * w[k + 1] + z4.z * w[k + 2] + z4.w * w[k + 3];
            }
            y1s[j][o] = leaky(a + b1o);
        }
        __syncthreads();
#pragma unroll
        for (int k = 0; k < 64; k++) w[k] = W2s[k][o];
        float m = -3.4e38f;
        for (int j = half * 10; j < half * 10 + 10; j++) {
            float a = 0.f;
#pragma unroll
            for (int k = 0; k < 64; k += 4) {
                float4 y4 = *(const float4*)&y1s[j][k];
                a += y4.x * w[k] + y4.y * w[k + 1] + y4.z * w[k + 2] + y4.w * w[k + 3];
            }
            m = fmaxf(m, a + b2o);
        }
        pm[half][o] = m;
        __syncthreads();
        if (tid < 64)
            g_h[(size_t)node * 192 + cv * 64 + tid] = fmaxf(pm[0][tid], pm[1][tid]);
    }
}

// ---------------- kernel 7: out = [h1|h2|hmax] @ Wl.T + bl + feature -------
__global__ void __launch_bounds__(256) k_final(const float* __restrict__ Wl,
                                               const float* __restrict__ bl,
                                               const float* __restrict__ feat,
                                               float* __restrict__ out) {
    __shared__ float hs[16][192];
    int tid = threadIdx.x;
    int r0 = blockIdx.x * 16;
    for (int i = tid; i < 16 * 192; i += 256) hs[i / 192][i % 192] = g_h[(size_t)r0 * 192 + i];
    __syncthreads();
    int o = tid;           // 256 outputs
    float acc[16] = {};
    for (int c = 0; c < 3; c++) {
        float4 w4[16];
        const float4* wp = (const float4*)(Wl + o * 192 + c * 64);
#pragma unroll
        for (int i = 0; i < 16; i++) w4[i] = wp[i];
#pragma unroll
        for (int r = 0; r < 16; r++) {
            const float4* xs = (const float4*)(&hs[r][c * 64]);
            float a = 0.f;
#pragma unroll
            for (int i = 0; i < 16; i++) {
                float4 x = xs[i];
                a += x.x * w4[i].x + x.y * w4[i].y + x.z * w4[i].z + x.w * w4[i].w;
            }
            acc[r] += a;
        }
    }
    float b = bl[o];
#pragma unroll
    for (int r = 0; r < 16; r++)
        out[(size_t)(r0 + r) * 256 + o] = acc[r] + b + feat[(size_t)(r0 + r) * 256 + o];
}

// ---------------- launch ---------------------------------------------------
extern "C" void kernel_launch(void* const* d_in, const int* in_sizes, int n_in,
                              void* d_out, int out_size) {
    const float* feature = (const float*)d_in[0];
    const float* Wb   = (const float*)d_in[1];
    const float* bb   = (const float*)d_in[2];
    const float* Wt1  = (const float*)d_in[3];
    const float* bt1  = (const float*)d_in[4];
    const float* Wp1  = (const float*)d_in[5];
    const float* bp1  = (const float*)d_in[6];
    const float* Wm1a = (const float*)d_in[7];
    const float* bm1a = (const float*)d_in[8];
    const float* Wm1b = (const float*)d_in[9];
    const float* bm1b = (const float*)d_in[10];
    const float* Wt2  = (const float*)d_in[11];
    const float* bt2  = (const float*)d_in[12];
    const float* Wp2  = (const float*)d_in[13];
    const float* bp2  = (const float*)d_in[14];
    const float* Wm2a = (const float*)d_in[15];
    const float* bm2a = (const float*)d_in[16];
    const float* Wm2b = (const float*)d_in[17];
    const float* bm2b = (const float*)d_in[18];
    const float* Wl   = (const float*)d_in[19];
    const float* bl   = (const float*)d_in[20];
    float* out = (float*)d_out;

    k_f<<<NPTS / 32, 256>>>(feature, Wb, bb);
    k_aux<<<dim3(NPTS / 16, 2), 256>>>(Wt1, bt1, Wp1, bp1, Wt2, bt2, Wp2, bp2);
    k_dist<<<dim3(NPTS / 64, NPTS / 64), 256>>>();
    k_select<<<NPTS, 256>>>();
    k_hmax<<<NPTS, 64>>>();
    k_edge<<<dim3(NPTS / ENODES, 2), 128>>>(Wm1a, bm1a, Wm1b, bm1b, Wm2a, bm2a, Wm2b, bm2b);
    k_final<<<NPTS / 16, 256>>>(Wl, bl, feature, out);
}

// round 5
// speedup vs baseline: 1.3005x; 1.1100x over previous
#include <cuda_runtime.h>
#include <stdint.h>

#define NPTS 8192
#define DIM  64
#define KSEL 40
#define SLOPE 0.01f

// ---------------- scratch (static __device__ per allocation rules) ----------
__device__ float g_f[NPTS * DIM];
__device__ float g_sq[NPTS];
__device__ float g_t[2][NPTS * DIM];
__device__ float g_c[2][NPTS * DIM];
__device__ float g_dist[(size_t)NPTS * NPTS];   // 256 MB
__device__ int   g_idx[NPTS * KSEL];
__device__ float g_h[NPTS * 192];               // [h1 | h2 | hmax]

__device__ __forceinline__ float leaky(float x) { return x >= 0.f ? x : SLOPE * x; }

// ---------------- kernel 1: f = feature @ Wb.T + bb ; sq = sum(f*f) --------
__global__ void __launch_bounds__(256) k_f(const float* __restrict__ feat,
                                           const float* __restrict__ Wb,
                                           const float* __restrict__ bb) {
    __shared__ float fs[32][256];   // 32 input rows
    __shared__ float fo[32][64];    // f outputs for sq reduction
    int tid = threadIdx.x;
    int r0 = blockIdx.x * 32;
    for (int i = tid; i < 32 * 256; i += 256) {
        int r = i >> 8, k = i & 255;
        fs[r][k] = feat[(size_t)(r0 + r) * 256 + k];
    }
    __syncthreads();
    int o  = tid & 63;
    int rg = tid >> 6;        // 4 groups of 8 rows
    float acc[8];
#pragma unroll
    for (int i = 0; i < 8; i++) acc[i] = bb[o];
    for (int c = 0; c < 4; c++) {
        float4 w4[16];
        const float4* wp = (const float4*)(Wb + o * 256 + c * 64);
#pragma unroll
        for (int i = 0; i < 16; i++) w4[i] = wp[i];
#pragma unroll
        for (int rr = 0; rr < 8; rr++) {
            int r = rg * 8 + rr;
            const float4* xs = (const float4*)(&fs[r][c * 64]);
            float a = 0.f;
#pragma unroll
            for (int i = 0; i < 16; i++) {
                float4 x = xs[i];
                a += x.x * w4[i].x + x.y * w4[i].y + x.z * w4[i].z + x.w * w4[i].w;
            }
            acc[rr] += a;
        }
    }
#pragma unroll
    for (int rr = 0; rr < 8; rr++) {
        int r = rg * 8 + rr;
        g_f[(size_t)(r0 + r) * 64 + o] = acc[rr];
        fo[r][o] = acc[rr];
    }
    __syncthreads();
    if (tid < 32) {                 // deterministic per-row square sum
        float s = 0.f;
#pragma unroll
        for (int k = 0; k < 64; k++) { float v = fo[tid][k]; s += v * v; }
        g_sq[r0 + tid] = s;
    }
}

// ---------------- kernel 2: t = f@Wt.T ; c = f@(Wp+Wt).T + bp + bt ---------
__global__ void __launch_bounds__(256) k_aux(const float* __restrict__ Wt1, const float* __restrict__ bt1,
                                             const float* __restrict__ Wp1, const float* __restrict__ bp1,
                                             const float* __restrict__ Wt2, const float* __restrict__ bt2,
                                             const float* __restrict__ Wp2, const float* __restrict__ bp2) {
    int set = blockIdx.y;
    const float* Wt = set ? Wt2 : Wt1;
    const float* bt = set ? bt2 : bt1;
    const float* Wp = set ? Wp2 : Wp1;
    const float* bp = set ? bp2 : bp1;

    __shared__ float fs[16][64];
    int tid = threadIdx.x;
    int r0 = blockIdx.x * 16;
    for (int i = tid; i < 16 * 64; i += 256) fs[i >> 6][i & 63] = g_f[(size_t)r0 * 64 + i];
    __syncthreads();
    int o = tid & 63, rg = tid >> 6;   // 4 rows per group
    float bsum = bt[o] + bp[o];

    float4 w4[16];
    const float4* wtp = (const float4*)(Wt + o * 64);
#pragma unroll
    for (int i = 0; i < 16; i++) w4[i] = wtp[i];
    float at[4];
#pragma unroll
    for (int rr = 0; rr < 4; rr++) {
        int r = rg * 4 + rr;
        const float4* xs = (const float4*)(&fs[r][0]);
        float a = 0.f;
#pragma unroll
        for (int i = 0; i < 16; i++) {
            float4 x = xs[i];
            a += x.x * w4[i].x + x.y * w4[i].y + x.z * w4[i].z + x.w * w4[i].w;
        }
        at[rr] = a;
        g_t[set][(size_t)(r0 + r) * 64 + o] = a;
    }
    const float4* wpp = (const float4*)(Wp + o * 64);
#pragma unroll
    for (int i = 0; i < 16; i++) w4[i] = wpp[i];
#pragma unroll
    for (int rr = 0; rr < 4; rr++) {
        int r = rg * 4 + rr;
        const float4* xs = (const float4*)(&fs[r][0]);
        float a = 0.f;
#pragma unroll
        for (int i = 0; i < 16; i++) {
            float4 x = xs[i];
            a += x.x * w4[i].x + x.y * w4[i].y + x.z * w4[i].z + x.w * w4[i].w;
        }
        g_c[set][(size_t)(r0 + r) * 64 + o] = at[rr] + a + bsum;
    }
}

// ---- kernel 3: pairwise distances, symmetric, 128x128 tile, 8x8/thread ----
// smem k-major with PAD=132 (16B-aligned rows; compute LDS.128 conflict-free)
#define DPAD 132
__global__ void __launch_bounds__(256) k_dist() {
    int bj = blockIdx.x, bi = blockIdx.y;
    if (bi > bj) return;                 // symmetry: upper triangle only

    __shared__ float As[32][DPAD];
    __shared__ float Bs[32][DPAD];
    __shared__ float sqa[128], sqb[128];
    int tid = threadIdx.x;
    int tx = tid & 15, ty = tid >> 4;
    int i0 = bi * 128, j0 = bj * 128;
    if (tid < 128) sqa[tid] = g_sq[i0 + tid];
    else           sqb[tid - 128] = g_sq[j0 + tid - 128];

    float acc[8][8] = {};
    for (int kk = 0; kk < 2; kk++) {
        __syncthreads();
        for (int idx = tid; idx < 4096; idx += 256) {
            int r = idx >> 5, k = idx & 31;           // coalesced LDG over k
            As[k][r] = g_f[(size_t)(i0 + r) * 64 + kk * 32 + k];
            Bs[k][r] = g_f[(size_t)(j0 + r) * 64 + kk * 32 + k];
        }
        __syncthreads();
#pragma unroll
        for (int k = 0; k < 32; k++) {
            float4 a0 = *(const float4*)&As[k][ty * 4];
            float4 a1 = *(const float4*)&As[k][64 + ty * 4];
            float4 b0 = *(const float4*)&Bs[k][tx * 4];
            float4 b1 = *(const float4*)&Bs[k][64 + tx * 4];
            float a[8] = { a0.x, a0.y, a0.z, a0.w, a1.x, a1.y, a1.z, a1.w };
            float b[8] = { b0.x, b0.y, b0.z, b0.w, b1.x, b1.y, b1.z, b1.w };
#pragma unroll
            for (int i = 0; i < 8; i++)
#pragma unroll
                for (int j = 0; j < 8; j++) acc[i][j] += a[i] * b[j];
        }
    }

    float dv[8][8];
#pragma unroll
    for (int i = 0; i < 8; i++) {
        int ri = (i < 4) ? ty * 4 + i : 64 + ty * 4 + (i - 4);
        float si = sqa[ri];
#pragma unroll
        for (int j = 0; j < 8; j++) {
            int cj = (j < 4) ? tx * 4 + j : 64 + tx * 4 + (j - 4);
            dv[i][j] = si + sqb[cj] - 2.f * acc[i][j];
        }
    }
    // direct stores (coalesced float4)
#pragma unroll
    for (int i = 0; i < 8; i++) {
        int ri = (i < 4) ? ty * 4 + i : 64 + ty * 4 + (i - 4);
        float* orow = &g_dist[(size_t)(i0 + ri) * NPTS + j0];
        *(float4*)&orow[tx * 4]      = make_float4(dv[i][0], dv[i][1], dv[i][2], dv[i][3]);
        *(float4*)&orow[64 + tx * 4] = make_float4(dv[i][4], dv[i][5], dv[i][6], dv[i][7]);
    }
    // mirror stores (transpose; 16B segments)
    if (bi != bj) {
#pragma unroll
        for (int j = 0; j < 8; j++) {
            int cj = (j < 4) ? tx * 4 + j : 64 + tx * 4 + (j - 4);
            float* orow = &g_dist[(size_t)(j0 + cj) * NPTS + i0];
            *(float4*)&orow[ty * 4]      = make_float4(dv[0][j], dv[1][j], dv[2][j], dv[3][j]);
            *(float4*)&orow[64 + ty * 4] = make_float4(dv[4][j], dv[5][j], dv[6][j], dv[7][j]);
        }
    }
}

// ---------------- kernel 4: exact sorted top-40 (lean sample select) -------
__device__ __forceinline__ unsigned fkey(float v) {
    unsigned b = __float_as_uint(v);
    return (b & 0x80000000u) ? ~b : (b | 0x80000000u);
}

__global__ void __launch_bounds__(256) k_select() {
    __shared__ float ssamp[256];                 // per-warp sorted samples
    __shared__ unsigned long long cand[1024];    // 8 KB
    __shared__ int scnt;
    __shared__ float sT;

    int tid  = threadIdx.x;
    int lane = tid & 31;
    int w    = tid >> 5;
    int row  = blockIdx.x;
    const float* drow = &g_dist[(size_t)row * NPTS];
    const float4* d4p = (const float4*)drow;

    // --- 256 samples; per-warp in-register bitonic sort (ascending by lane)
    float v = drow[tid * 32 + 16];
#pragma unroll
    for (int k = 2; k <= 32; k <<= 1) {
#pragma unroll
        for (int j = k >> 1; j > 0; j >>= 1) {
            float o = __shfl_xor_sync(0xFFFFFFFFu, v, j);
            bool takeMin = (((lane & k) == 0) == ((lane & j) == 0));
            v = takeMin ? fminf(v, o) : fmaxf(v, o);
        }
    }
    ssamp[w * 32 + lane] = v;
    __syncthreads();

    // --- warp 0: T = 5th smallest of union(per-warp top-5) = global samp[4]
    if (w == 0) {
        int i1 = 32 + lane;
        float a = ssamp[(lane / 5) * 32 + (lane % 5)];
        float b = (lane < 8) ? ssamp[(i1 / 5) * 32 + (i1 % 5)] : 3.4e38f;
        float T = 0.f;
#pragma unroll
        for (int it = 0; it < 5; it++) {
            float m = fminf(a, b);
#pragma unroll
            for (int s = 16; s; s >>= 1) m = fminf(m, __shfl_xor_sync(0xFFFFFFFFu, m, s));
            unsigned own = __ballot_sync(0xFFFFFFFFu, a == m || b == m);
            int first = __ffs(own) - 1;
            if (lane == first) { if (a == m) a = 3.4e38f; else b = 3.4e38f; }
            T = m;
        }
        if (lane == 0) sT = T;
    }
    __syncthreads();

    // --- stream row, warp-scan compaction; rare fallback ladder on failure
    float T = sT;
    int C = 0;
    bool fallback_sorted = false;
    int r = 4;
    for (int attempt = 0; attempt < 16; attempt++) {
        __syncthreads();
        if (tid == 0) scnt = 0;
        __syncthreads();
        for (int q = tid; q < NPTS / 4; q += 256) {
            float4 d = d4p[q];
            bool p0 = d.x < T, p1 = d.y < T, p2 = d.z < T, p3 = d.w < T;
            int cnt = (int)p0 + (int)p1 + (int)p2 + (int)p3;
            unsigned bm = __ballot_sync(0xFFFFFFFFu, cnt != 0);
            if (!bm) continue;
            int off = cnt;
#pragma unroll
            for (int s = 1; s < 32; s <<= 1) {
                int t2 = __shfl_up_sync(0xFFFFFFFFu, off, s);
                if (lane >= s) off += t2;
            }
            int tot = __shfl_sync(0xFFFFFFFFu, off, 31);
            int base = 0;
            if (lane == 31) base = atomicAdd(&scnt, tot);
            base = __shfl_sync(0xFFFFFFFFu, base, 31);
            int pos = base + off - cnt;
            int j = q * 4;
            if (p0) { if (pos < 1024) cand[pos] = ((unsigned long long)fkey(d.x) << 32) | (unsigned)(j + 0); pos++; }
            if (p1) { if (pos < 1024) cand[pos] = ((unsigned long long)fkey(d.y) << 32) | (unsigned)(j + 1); pos++; }
            if (p2) { if (pos < 1024) cand[pos] = ((unsigned long long)fkey(d.z) << 32) | (unsigned)(j + 2); pos++; }
            if (p3) { if (pos < 1024) cand[pos] = ((unsigned long long)fkey(d.w) << 32) | (unsigned)(j + 3); pos++; }
        }
        __syncthreads();
        C = scnt;
        if (C >= KSEL && C <= 1024) break;
        // rare path: sort all 256 samples once, then walk rank ladder
        if (!fallback_sorted) {
            fallback_sorted = true;
            for (int size = 2; size <= 256; size <<= 1) {
                for (int stride = size >> 1; stride > 0; stride >>= 1) {
                    __syncthreads();
                    int i = tid, ixj = i ^ stride;
                    if (ixj > i) {
                        float x = ssamp[i], y = ssamp[ixj];
                        bool up = (i & size) == 0;
                        if ((x > y) == up) { ssamp[i] = y; ssamp[ixj] = x; }
                    }
                }
            }
            __syncthreads();
        }
        if (C < KSEL) r = (r * 3 > 255) ? 255 : r * 3;
        else          r = (r <= 1) ? 1 : (r >> 1);
        T = ssamp[r];
        __syncthreads();
    }

    int Cc = C < 1024 ? C : 1024;
    int S = 64;
    while (S < Cc) S <<= 1;          // S in {64..1024}
    for (int i = Cc + tid; i < S; i += 256) cand[i] = 0xFFFFFFFFFFFFFFFFull;
    __syncthreads();

    // bitonic sort S candidates: (key asc, idx asc) via packed compare
    for (int size = 2; size <= S; size <<= 1) {
        for (int stride = size >> 1; stride > 0; stride >>= 1) {
            for (int i = tid; i < S; i += 256) {
                int ixj = i ^ stride;
                if (ixj > i) {
                    bool up = (i & size) == 0;
                    unsigned long long a = cand[i], b = cand[ixj];
                    if ((a > b) == up) { cand[i] = b; cand[ixj] = a; }
                }
            }
            __syncthreads();
        }
    }
    if (tid < KSEL) g_idx[row * KSEL + tid] = (int)(cand[tid] & 0xFFFFFFFFull);
}

// ---------------- kernel 5: edge conv (+hmax fused on cv=0), 8 nodes/block -
#define ENODES 8
__global__ void __launch_bounds__(128) k_edge(const float* __restrict__ Wa1, const float* __restrict__ ba1,
                                              const float* __restrict__ Wb1, const float* __restrict__ bb1,
                                              const float* __restrict__ Wa2, const float* __restrict__ ba2,
                                              const float* __restrict__ Wb2, const float* __restrict__ bb2) {
    int cv = blockIdx.y;
    const float* Wa  = cv ? Wa2 : Wa1;
    const float* ba  = cv ? ba2 : ba1;
    const float* Wb_ = cv ? Wb2 : Wb1;
    const float* bbv = cv ? bb2 : bb1;

    __shared__ float W1s[64][65];   // [k][o] transposed
    __shared__ float W2s[64][65];
    __shared__ float zs[20][64];
    __shared__ float y1s[20][64];
    __shared__ float cs[64];
    __shared__ int   nb[20];
    __shared__ float pm[2][64];

    int tid = threadIdx.x;
    for (int i = tid; i < 4096; i += 128) {
        int o = i >> 6, k = i & 63;
        W1s[k][o] = Wa[i];
        W2s[k][o] = Wb_[i];
    }
    int o = tid & 63, half = tid >> 6;
    float b1o = ba[o], b2o = bbv[o];

    for (int nn = 0; nn < ENODES; nn++) {
        int node = blockIdx.x * ENODES + nn;
        __syncthreads();   // also covers initial weight-staging barrier
        if (tid < 64) cs[tid] = g_c[cv][(size_t)node * 64 + tid];
        if (tid < 20) nb[tid] = g_idx[node * KSEL + (cv ? tid * 2 : tid)];
        __syncthreads();

        for (int e = tid; e < 20 * 64; e += 128) {
            int j = e >> 6, k = e & 63;
            zs[j][k] = leaky(cs[k] - g_t[cv][(size_t)nb[j] * 64 + k]);
        }
        // fused hmax (first 9 neighbors of idx40 == nb[0..8] when cv==0)
        if (cv == 0 && tid < 64) {
            float m = -3.4e38f;
#pragma unroll
            for (int j = 0; j < 9; j++) m = fmaxf(m, g_f[(size_t)nb[j] * 64 + tid]);
            g_h[(size_t)node * 192 + 128 + tid] = m;
        }
        __syncthreads();

        float w[64];
#pragma unroll
        for (int k = 0; k < 64; k++) w[k] = W1s[k][o];
        for (int j = half * 10; j < half * 10 + 10; j++) {
            float a = 0.f;
#pragma unroll
            for (int k = 0; k < 64; k += 4) {
                float4 z4 = *(const float4*)&zs[j][k];
                a += z4.x * w[k] + z4.y * w[k + 1] + z4.z * w[k + 2] + z4.w * w[k + 3];
            }
            y1s[j][o] = leaky(a + b1o);
        }
        __syncthreads();
#pragma unroll
        for (int k = 0; k < 64; k++) w[k] = W2s[k][o];
        float m = -3.4e38f;
        for (int j = half * 10; j < half * 10 + 10; j++) {
            float a = 0.f;
#pragma unroll
            for (int k = 0; k < 64; k += 4) {
                float4 y4 = *(const float4*)&y1s[j][k];
                a += y4.x * w[k] + y4.y * w[k + 1] + y4.z * w[k + 2] + y4.w * w[k + 3];
            }
            m = fmaxf(m, a + b2o);
        }
        pm[half][o] = m;
        __syncthreads();
        if (tid < 64)
            g_h[(size_t)node * 192 + cv * 64 + tid] = fmaxf(pm[0][tid], pm[1][tid]);
    }
}

// ---------------- kernel 6: out = [h1|h2|hmax] @ Wl.T + bl + feature -------
__global__ void __launch_bounds__(256) k_final(const float* __restrict__ Wl,
                                               const float* __restrict__ bl,
                                               const float* __restrict__ feat,
                                               float* __restrict__ out) {
    __shared__ float hs[16][192];
    int tid = threadIdx.x;
    int r0 = blockIdx.x * 16;
    for (int i = tid; i < 16 * 192; i += 256) hs[i / 192][i % 192] = g_h[(size_t)r0 * 192 + i];
    __syncthreads();
    int o = tid;           // 256 outputs
    float acc[16] = {};
    for (int c = 0; c < 3; c++) {
        float4 w4[16];
        const float4* wp = (const float4*)(Wl + o * 192 + c * 64);
#pragma unroll
        for (int i = 0; i < 16; i++) w4[i] = wp[i];
#pragma unroll
        for (int r = 0; r < 16; r++) {
            const float4* xs = (const float4*)(&hs[r][c * 64]);
            float a = 0.f;
#pragma unroll
            for (int i = 0; i < 16; i++) {
                float4 x = xs[i];
                a += x.x * w4[i].x + x.y * w4[i].y + x.z * w4[i].z + x.w * w4[i].w;
            }
            acc[r] += a;
        }
    }
    float b = bl[o];
#pragma unroll
    for (int r = 0; r < 16; r++)
        out[(size_t)(r0 + r) * 256 + o] = acc[r] + b + feat[(size_t)(r0 + r) * 256 + o];
}

// ---------------- launch ---------------------------------------------------
extern "C" void kernel_launch(void* const* d_in, const int* in_sizes, int n_in,
                              void* d_out, int out_size) {
    const float* feature = (const float*)d_in[0];
    const float* Wb   = (const float*)d_in[1];
    const float* bb   = (const float*)d_in[2];
    const float* Wt1  = (const float*)d_in[3];
    const float* bt1  = (const float*)d_in[4];
    const float* Wp1  = (const float*)d_in[5];
    const float* bp1  = (const float*)d_in[6];
    const float* Wm1a = (const float*)d_in[7];
    const float* bm1a = (const float*)d_in[8];
    const float* Wm1b = (const float*)d_in[9];
    const float* bm1b = (const float*)d_in[10];
    const float* Wt2  = (const float*)d_in[11];
    const float* bt2  = (const float*)d_in[12];
    const float* Wp2  = (const float*)d_in[13];
    const float* bp2  = (const float*)d_in[14];
    const float* Wm2a = (const float*)d_in[15];
    const float* bm2a = (const float*)d_in[16];
    const float* Wm2b = (const float*)d_in[17];
    const float* bm2b = (const float*)d_in[18];
    const float* Wl   = (const float*)d_in[19];
    const float* bl   = (const float*)d_in[20];
    float* out = (float*)d_out;

    k_f<<<NPTS / 32, 256>>>(feature, Wb, bb);
    k_aux<<<dim3(NPTS / 16, 2), 256>>>(Wt1, bt1, Wp1, bp1, Wt2, bt2, Wp2, bp2);
    k_dist<<<dim3(NPTS / 128, NPTS / 128), 256>>>();
    k_select<<<NPTS, 256>>>();
    k_edge<<<dim3(NPTS / ENODES, 2), 128>>>(Wm1a, bm1a, Wm1b, bm1b, Wm2a, bm2a, Wm2b, bm2b);
    k_final<<<NPTS / 16, 256>>>(Wl, bl, feature, out);
}